// round 15
// baseline (speedup 1.0000x reference)
#include <cuda_runtime.h>

#define T_STEPS 2000
#define N_IN    8192
#define N_OUT   4096

__device__ float g_lif[(size_t)T_STEPS * N_OUT];
__device__ int   g_done[16][32];     // per-tile completion flags

constexpr int BM = 128, BN = 128, BK = 8, TM = 8, TN = 8;
constexpr int M_BLK = 16, N_BLK = 32;

__global__ void zero_flags_kernel() {
    int* p = &g_done[0][0];
    for (int i = threadIdx.x; i < M_BLK * N_BLK; i += 128) p[i] = 0;
}

__device__ __forceinline__ int ld_acquire_gpu(const int* p) {
    int v;
    asm volatile("ld.acquire.gpu.s32 %0, [%1];" : "=r"(v) : "l"(p) : "memory");
    return v;
}
__device__ __forceinline__ void st_release_gpu(int* p, int v) {
    asm volatile("st.release.gpu.s32 [%0], %1;" :: "l"(p), "r"(v) : "memory");
}

// ---------------------------------------------------------------------------
// GEMM — R12's double-buffered kernel, math byte-identical (ascending-k fp32
// fma chain per output). Epilogue: per-tile release flag (single writer).
// ---------------------------------------------------------------------------
__global__ __launch_bounds__(256, 2)
void gemm_nt_kernel(const float* __restrict__ A,
                    const float* __restrict__ B,
                    float* __restrict__ C,
                    int M, int N, int K)
{
    __shared__ float As[2][BK][BM];
    __shared__ float Bs[2][BK][BN];

    const int tid = threadIdx.x;
    const int bm  = blockIdx.y * BM;
    const int bn  = blockIdx.x * BN;

    const int loadRow = tid >> 1;
    const int loadCol = (tid & 1) * 4;
    const int tr = (tid >> 4) * TM;
    const int tc = (tid & 15) * TN;

    float acc[TM][TN];
    #pragma unroll
    for (int i = 0; i < TM; i++)
        #pragma unroll
        for (int j = 0; j < TN; j++)
            acc[i][j] = 0.0f;

    const bool aValid = (bm + loadRow) < M;
    const float* Aptr = A + (size_t)(bm + loadRow) * K + loadCol;
    const float* Bptr = B + (size_t)(bn + loadRow) * K + loadCol;

    float4 a4 = aValid ? *(const float4*)(Aptr) : make_float4(0.f, 0.f, 0.f, 0.f);
    float4 b4 = *(const float4*)(Bptr);

    int s = 0;
    for (int k0 = 0; k0 < K; k0 += BK) {
        As[s][loadCol + 0][loadRow] = a4.x;
        As[s][loadCol + 1][loadRow] = a4.y;
        As[s][loadCol + 2][loadRow] = a4.z;
        As[s][loadCol + 3][loadRow] = a4.w;
        Bs[s][loadCol + 0][loadRow] = b4.x;
        Bs[s][loadCol + 1][loadRow] = b4.y;
        Bs[s][loadCol + 2][loadRow] = b4.z;
        Bs[s][loadCol + 3][loadRow] = b4.w;
        __syncthreads();

        if (k0 + BK < K) {
            a4 = aValid ? *(const float4*)(Aptr + k0 + BK)
                        : make_float4(0.f, 0.f, 0.f, 0.f);
            b4 = *(const float4*)(Bptr + k0 + BK);
        }

        #pragma unroll
        for (int k = 0; k < BK; k++) {
            float ar[TM], br[TN];
            #pragma unroll
            for (int i = 0; i < TM; i++) ar[i] = As[s][k][tr + i];
            #pragma unroll
            for (int j = 0; j < TN; j++) br[j] = Bs[s][k][tc + j];
            #pragma unroll
            for (int i = 0; i < TM; i++)
                #pragma unroll
                for (int j = 0; j < TN; j++)
                    acc[i][j] += ar[i] * br[j];   // ascending-k fma chain
        }
        s ^= 1;
    }

    #pragma unroll
    for (int i = 0; i < TM; i++) {
        int gm = bm + tr + i;
        if (gm < M) {
            float* Crow = C + (size_t)gm * N + bn + tc;
            #pragma unroll
            for (int j = 0; j < TN; j += 4) {
                float4 v = make_float4(acc[i][j], acc[i][j+1],
                                       acc[i][j+2], acc[i][j+3]);
                *(float4*)(Crow + j) = v;
            }
        }
    }

    __threadfence();
    __syncthreads();
    if (tid == 0) st_release_gpu(&g_done[blockIdx.y][blockIdx.x], 1);
}

// ---------------------------------------------------------------------------
// LIF scan — overlapped consumer. Scan CTA `bid` touches only columns
// [bid*32, bid*32+32) == n-tile bid>>2, so it waits on THAT tile's flag only.
// Per-step values identical to the rel_err-0.0 form.
// ---------------------------------------------------------------------------
__device__ __forceinline__ float lif_step(float inp, float& v, float& refrac,
                                          float dt_tau, float rest, float th,
                                          float rst, float trf)
{
    const float DT = 0.001f;
    float v1 = v - dt_tau * (v - rest);
    float va = v1 + inp;
    v1 = (refrac == 0.0f) ? va : v1;
    float rf = refrac - DT;
    rf = (refrac > 0.0f) ? rf : 0.0f;
    bool p = (v1 >= th);                 // == (v1 - th >= 0)
    float spike = p ? 1.0f : 0.0f;
    refrac = p ? trf : rf;
    v = p ? rst : v1;
    return spike;
}

__global__ __launch_bounds__(32)
void lif_scan_kernel(const float* __restrict__ lif,
                     float* __restrict__ out,
                     const float* __restrict__ v_th,
                     const float* __restrict__ v_rest,
                     const float* __restrict__ v_reset,
                     const float* __restrict__ t_ref,
                     const float* __restrict__ tau)
{
    const int bid = blockIdx.x;
    const int n = bid * 32 + threadIdx.x;   // 128*32 = 4096
    const int ntile = bid >> 2;             // the single n-tile this CTA reads

    const float th   = v_th[n];
    const float rest = v_rest[n];
    const float rst  = v_reset[n];
    const float trf  = t_ref[n];
    const float dt_tau = 0.001f * tau[n];

    float v = rest;
    float refrac = 0.0f;
    out[n] = 0.0f;

    for (int b = 0; b < M_BLK; b++) {
        const int t0 = (b == 0) ? 1 : b * BM;
        const int t1 = (b + 1) * BM < T_STEPS ? (b + 1) * BM : T_STEPS;

        // wait only for OUR tile of m-block b
        while (ld_acquire_gpu(&g_done[b][ntile]) == 0) __nanosleep(128);
        __syncwarp();

        int t = t0;
        while (t + 16 <= t1) {
            float buf[16];
            #pragma unroll
            for (int j = 0; j < 16; j++)
                buf[j] = lif[(size_t)(t + j) * N_OUT + n];
            #pragma unroll
            for (int j = 0; j < 16; j++)
                out[(size_t)(t + j) * N_OUT + n] =
                    lif_step(buf[j], v, refrac, dt_tau, rest, th, rst, trf);
            t += 16;
        }
        while (t < t1) {
            float inp = lif[(size_t)t * N_OUT + n];
            out[(size_t)t * N_OUT + n] =
                lif_step(inp, v, refrac, dt_tau, rest, th, rst, trf);
            t++;
        }
    }
}

// ---------------------------------------------------------------------------
extern "C" void kernel_launch(void* const* d_in, const int* in_sizes, int n_in,
                              void* d_out, int out_size)
{
    const float* x       = (const float*)d_in[0];
    const float* weight  = (const float*)d_in[1];
    const float* v_th    = (const float*)d_in[2];
    const float* v_rest  = (const float*)d_in[3];
    const float* v_reset = (const float*)d_in[4];
    const float* t_ref   = (const float*)d_in[5];
    const float* tau     = (const float*)d_in[6];
    float* out = (float*)d_out;

    float* lif_ptr = nullptr;
    cudaGetSymbolAddress((void**)&lif_ptr, g_lif);

    cudaStream_t s2;
    cudaEvent_t ev0, ev1;
    cudaStreamCreateWithFlags(&s2, cudaStreamNonBlocking);
    cudaEventCreateWithFlags(&ev0, cudaEventDisableTiming);
    cudaEventCreateWithFlags(&ev1, cudaEventDisableTiming);

    // reset flags, then fork
    zero_flags_kernel<<<1, 128>>>();
    cudaEventRecord(ev0, 0);
    cudaStreamWaitEvent(s2, ev0, 0);

    // producer: 16 x 32 tiles of 128x128 (R12 GEMM)
    dim3 grid(N_OUT / BN, (T_STEPS + BM - 1) / BM);
    gemm_nt_kernel<<<grid, 256>>>(x, weight, lif_ptr, T_STEPS, N_OUT, N_IN);

    // consumer: overlapped scan (per-tile waits)
    lif_scan_kernel<<<128, 32, 0, s2>>>(lif_ptr, out,
                                        v_th, v_rest, v_reset, t_ref, tau);

    // join
    cudaEventRecord(ev1, s2);
    cudaStreamWaitEvent(0, ev1, 0);
}

// round 16
// speedup vs baseline: 1.0585x; 1.0585x over previous
#include <cuda_runtime.h>

#define T_STEPS 2000
#define N_IN    8192
#define N_OUT   4096

__device__ float g_lif[(size_t)T_STEPS * N_OUT];
__device__ int   g_flags[16];

constexpr int BM = 128, BN = 128, BK = 8, TM = 8, TN = 8;
constexpr int M_BLK = 16, N_BLK = 32;

__global__ void zero_flags_kernel() {
    if (threadIdx.x < M_BLK) g_flags[threadIdx.x] = 0;
}

__device__ __forceinline__ int ld_acquire_gpu(const int* p) {
    int v;
    asm volatile("ld.acquire.gpu.s32 %0, [%1];" : "=r"(v) : "l"(p) : "memory");
    return v;
}

// ---------------------------------------------------------------------------
// GEMM — double-buffered 128x128/BK=8/8x8 SGEMM at the fp32 pipe ceiling.
// Per-output ascending-k fp32 fma chain (bit-exact vs reference).
// Epilogue: per-m-block completion flag.
// ---------------------------------------------------------------------------
__global__ __launch_bounds__(256, 2)
void gemm_nt_kernel(const float* __restrict__ A,
                    const float* __restrict__ B,
                    float* __restrict__ C,
                    int M, int N, int K)
{
    __shared__ float As[2][BK][BM];
    __shared__ float Bs[2][BK][BN];

    const int tid = threadIdx.x;
    const int bm  = blockIdx.y * BM;
    const int bn  = blockIdx.x * BN;

    const int loadRow = tid >> 1;
    const int loadCol = (tid & 1) * 4;
    const int tr = (tid >> 4) * TM;
    const int tc = (tid & 15) * TN;

    float acc[TM][TN];
    #pragma unroll
    for (int i = 0; i < TM; i++)
        #pragma unroll
        for (int j = 0; j < TN; j++)
            acc[i][j] = 0.0f;

    const bool aValid = (bm + loadRow) < M;
    const float* Aptr = A + (size_t)(bm + loadRow) * K + loadCol;
    const float* Bptr = B + (size_t)(bn + loadRow) * K + loadCol;

    float4 a4 = aValid ? *(const float4*)(Aptr) : make_float4(0.f, 0.f, 0.f, 0.f);
    float4 b4 = *(const float4*)(Bptr);

    int s = 0;
    for (int k0 = 0; k0 < K; k0 += BK) {
        As[s][loadCol + 0][loadRow] = a4.x;
        As[s][loadCol + 1][loadRow] = a4.y;
        As[s][loadCol + 2][loadRow] = a4.z;
        As[s][loadCol + 3][loadRow] = a4.w;
        Bs[s][loadCol + 0][loadRow] = b4.x;
        Bs[s][loadCol + 1][loadRow] = b4.y;
        Bs[s][loadCol + 2][loadRow] = b4.z;
        Bs[s][loadCol + 3][loadRow] = b4.w;
        __syncthreads();

        if (k0 + BK < K) {
            a4 = aValid ? *(const float4*)(Aptr + k0 + BK)
                        : make_float4(0.f, 0.f, 0.f, 0.f);
            b4 = *(const float4*)(Bptr + k0 + BK);
        }

        #pragma unroll
        for (int k = 0; k < BK; k++) {
            float ar[TM], br[TN];
            #pragma unroll
            for (int i = 0; i < TM; i++) ar[i] = As[s][k][tr + i];
            #pragma unroll
            for (int j = 0; j < TN; j++) br[j] = Bs[s][k][tc + j];
            #pragma unroll
            for (int i = 0; i < TM; i++)
                #pragma unroll
                for (int j = 0; j < TN; j++)
                    acc[i][j] += ar[i] * br[j];   // ascending-k fma chain
        }
        s ^= 1;
    }

    #pragma unroll
    for (int i = 0; i < TM; i++) {
        int gm = bm + tr + i;
        if (gm < M) {
            float* Crow = C + (size_t)gm * N + bn + tc;
            #pragma unroll
            for (int j = 0; j < TN; j += 4) {
                float4 v = make_float4(acc[i][j], acc[i][j+1],
                                       acc[i][j+2], acc[i][j+3]);
                *(float4*)(Crow + j) = v;
            }
        }
    }

    __threadfence();
    __syncthreads();
    if (tid == 0) atomicAdd(&g_flags[blockIdx.y], 1);
}

// ---------------------------------------------------------------------------
// LIF scan — overlapped consumer, per-step values identical to the
// rel_err-0.0 form; one FSETP drives all selects.
// ---------------------------------------------------------------------------
__device__ __forceinline__ float lif_step(float inp, float& v, float& refrac,
                                          float dt_tau, float rest, float th,
                                          float rst, float trf)
{
    const float DT = 0.001f;
    float v1 = v - dt_tau * (v - rest);
    float va = v1 + inp;
    v1 = (refrac == 0.0f) ? va : v1;
    float rf = refrac - DT;
    rf = (refrac > 0.0f) ? rf : 0.0f;
    bool p = (v1 >= th);                 // == (v1 - th >= 0)
    float spike = p ? 1.0f : 0.0f;
    refrac = p ? trf : rf;
    v = p ? rst : v1;
    return spike;
}

__global__ __launch_bounds__(32)
void lif_scan_kernel(const float* __restrict__ lif,
                     float* __restrict__ out,
                     const float* __restrict__ v_th,
                     const float* __restrict__ v_rest,
                     const float* __restrict__ v_reset,
                     const float* __restrict__ t_ref,
                     const float* __restrict__ tau)
{
    const int n = blockIdx.x * 32 + threadIdx.x;   // 128*32 = 4096

    const float th   = v_th[n];
    const float rest = v_rest[n];
    const float rst  = v_reset[n];
    const float trf  = t_ref[n];
    const float dt_tau = 0.001f * tau[n];

    float v = rest;
    float refrac = 0.0f;
    out[n] = 0.0f;

    for (int b = 0; b < M_BLK; b++) {
        const int t0 = (b == 0) ? 1 : b * BM;
        const int t1 = (b + 1) * BM < T_STEPS ? (b + 1) * BM : T_STEPS;

        // wait for all 32 n-tiles of m-block b (all lanes poll same word)
        while (ld_acquire_gpu(&g_flags[b]) < N_BLK) __nanosleep(128);
        __syncwarp();

        int t = t0;
        while (t + 16 <= t1) {
            float buf[16];
            #pragma unroll
            for (int j = 0; j < 16; j++)
                buf[j] = lif[(size_t)(t + j) * N_OUT + n];
            #pragma unroll
            for (int j = 0; j < 16; j++)
                out[(size_t)(t + j) * N_OUT + n] =
                    lif_step(buf[j], v, refrac, dt_tau, rest, th, rst, trf);
            t += 16;
        }
        while (t < t1) {
            float inp = lif[(size_t)t * N_OUT + n];
            out[(size_t)t * N_OUT + n] =
                lif_step(inp, v, refrac, dt_tau, rest, th, rst, trf);
            t++;
        }
    }
}

// ---------------------------------------------------------------------------
extern "C" void kernel_launch(void* const* d_in, const int* in_sizes, int n_in,
                              void* d_out, int out_size)
{
    const float* x       = (const float*)d_in[0];
    const float* weight  = (const float*)d_in[1];
    const float* v_th    = (const float*)d_in[2];
    const float* v_rest  = (const float*)d_in[3];
    const float* v_reset = (const float*)d_in[4];
    const float* t_ref   = (const float*)d_in[5];
    const float* tau     = (const float*)d_in[6];
    float* out = (float*)d_out;

    float* lif_ptr = nullptr;
    cudaGetSymbolAddress((void**)&lif_ptr, g_lif);

    // fork resources (created per call; a handful of calls total, no device mem)
    cudaStream_t s2;
    cudaEvent_t ev0, ev1;
    cudaStreamCreateWithFlags(&s2, cudaStreamNonBlocking);
    cudaEventCreateWithFlags(&ev0, cudaEventDisableTiming);
    cudaEventCreateWithFlags(&ev1, cudaEventDisableTiming);

    // main stream: reset flags, then fork
    zero_flags_kernel<<<1, 32>>>();
    cudaEventRecord(ev0, 0);
    cudaStreamWaitEvent(s2, ev0, 0);

    // branch A (main stream): GEMM producer
    dim3 grid(N_OUT / BN, (T_STEPS + BM - 1) / BM);
    gemm_nt_kernel<<<grid, 256>>>(x, weight, lif_ptr, T_STEPS, N_OUT, N_IN);

    // branch B (s2): scan consumer, polls per-m-block flags
    lif_scan_kernel<<<128, 32, 0, s2>>>(lif_ptr, out,
                                        v_th, v_rest, v_reset, t_ref, tau);

    // join
    cudaEventRecord(ev1, s2);
    cudaStreamWaitEvent(0, ev1, 0);
}

// round 17
// speedup vs baseline: 1.0591x; 1.0005x over previous
#include <cuda_runtime.h>

#define T_STEPS 2000
#define N_IN    8192
#define N_OUT   4096

__device__ float g_lif[(size_t)T_STEPS * N_OUT];
__device__ int   g_flags[16];        // zero-initialized; self-reset each call
__device__ int   g_scan_done;        // count of finished scan CTAs

constexpr int BM = 128, BN = 128, BK = 8, TM = 8, TN = 8;
constexpr int M_BLK = 16, N_BLK = 32;
constexpr int SCAN_CTAS = 128;

__device__ __forceinline__ int ld_acquire_gpu(const int* p) {
    int v;
    asm volatile("ld.acquire.gpu.s32 %0, [%1];" : "=r"(v) : "l"(p) : "memory");
    return v;
}

// ---------------------------------------------------------------------------
// GEMM — double-buffered 128x128/BK=8/8x8 SGEMM at the fp32 pipe ceiling.
// Per-output ascending-k fp32 fma chain (bit-exact vs reference).
// Epilogue: per-m-block completion flag.
// ---------------------------------------------------------------------------
__global__ __launch_bounds__(256, 2)
void gemm_nt_kernel(const float* __restrict__ A,
                    const float* __restrict__ B,
                    float* __restrict__ C,
                    int M, int N, int K)
{
    __shared__ float As[2][BK][BM];
    __shared__ float Bs[2][BK][BN];

    const int tid = threadIdx.x;
    const int bm  = blockIdx.y * BM;
    const int bn  = blockIdx.x * BN;

    const int loadRow = tid >> 1;
    const int loadCol = (tid & 1) * 4;
    const int tr = (tid >> 4) * TM;
    const int tc = (tid & 15) * TN;

    float acc[TM][TN];
    #pragma unroll
    for (int i = 0; i < TM; i++)
        #pragma unroll
        for (int j = 0; j < TN; j++)
            acc[i][j] = 0.0f;

    const bool aValid = (bm + loadRow) < M;
    const float* Aptr = A + (size_t)(bm + loadRow) * K + loadCol;
    const float* Bptr = B + (size_t)(bn + loadRow) * K + loadCol;

    float4 a4 = aValid ? *(const float4*)(Aptr) : make_float4(0.f, 0.f, 0.f, 0.f);
    float4 b4 = *(const float4*)(Bptr);

    int s = 0;
    for (int k0 = 0; k0 < K; k0 += BK) {
        As[s][loadCol + 0][loadRow] = a4.x;
        As[s][loadCol + 1][loadRow] = a4.y;
        As[s][loadCol + 2][loadRow] = a4.z;
        As[s][loadCol + 3][loadRow] = a4.w;
        Bs[s][loadCol + 0][loadRow] = b4.x;
        Bs[s][loadCol + 1][loadRow] = b4.y;
        Bs[s][loadCol + 2][loadRow] = b4.z;
        Bs[s][loadCol + 3][loadRow] = b4.w;
        __syncthreads();

        if (k0 + BK < K) {
            a4 = aValid ? *(const float4*)(Aptr + k0 + BK)
                        : make_float4(0.f, 0.f, 0.f, 0.f);
            b4 = *(const float4*)(Bptr + k0 + BK);
        }

        #pragma unroll
        for (int k = 0; k < BK; k++) {
            float ar[TM], br[TN];
            #pragma unroll
            for (int i = 0; i < TM; i++) ar[i] = As[s][k][tr + i];
            #pragma unroll
            for (int j = 0; j < TN; j++) br[j] = Bs[s][k][tc + j];
            #pragma unroll
            for (int i = 0; i < TM; i++)
                #pragma unroll
                for (int j = 0; j < TN; j++)
                    acc[i][j] += ar[i] * br[j];   // ascending-k fma chain
        }
        s ^= 1;
    }

    #pragma unroll
    for (int i = 0; i < TM; i++) {
        int gm = bm + tr + i;
        if (gm < M) {
            float* Crow = C + (size_t)gm * N + bn + tc;
            #pragma unroll
            for (int j = 0; j < TN; j += 4) {
                float4 v = make_float4(acc[i][j], acc[i][j+1],
                                       acc[i][j+2], acc[i][j+3]);
                *(float4*)(Crow + j) = v;
            }
        }
    }

    __threadfence();
    __syncthreads();
    if (tid == 0) atomicAdd(&g_flags[blockIdx.y], 1);
}

// ---------------------------------------------------------------------------
// LIF scan — overlapped consumer, per-step values identical to the
// rel_err-0.0 form. Last CTA out resets the flags for the next graph replay.
// ---------------------------------------------------------------------------
__device__ __forceinline__ float lif_step(float inp, float& v, float& refrac,
                                          float dt_tau, float rest, float th,
                                          float rst, float trf)
{
    const float DT = 0.001f;
    float v1 = v - dt_tau * (v - rest);
    float va = v1 + inp;
    v1 = (refrac == 0.0f) ? va : v1;
    float rf = refrac - DT;
    rf = (refrac > 0.0f) ? rf : 0.0f;
    bool p = (v1 >= th);                 // == (v1 - th >= 0)
    float spike = p ? 1.0f : 0.0f;
    refrac = p ? trf : rf;
    v = p ? rst : v1;
    return spike;
}

__global__ __launch_bounds__(32)
void lif_scan_kernel(const float* __restrict__ lif,
                     float* __restrict__ out,
                     const float* __restrict__ v_th,
                     const float* __restrict__ v_rest,
                     const float* __restrict__ v_reset,
                     const float* __restrict__ t_ref,
                     const float* __restrict__ tau)
{
    const int n = blockIdx.x * 32 + threadIdx.x;   // 128*32 = 4096

    const float th   = v_th[n];
    const float rest = v_rest[n];
    const float rst  = v_reset[n];
    const float trf  = t_ref[n];
    const float dt_tau = 0.001f * tau[n];

    float v = rest;
    float refrac = 0.0f;
    out[n] = 0.0f;

    for (int b = 0; b < M_BLK; b++) {
        const int t0 = (b == 0) ? 1 : b * BM;
        const int t1 = (b + 1) * BM < T_STEPS ? (b + 1) * BM : T_STEPS;

        // wait for all 32 n-tiles of m-block b (all lanes poll same word)
        while (ld_acquire_gpu(&g_flags[b]) < N_BLK) __nanosleep(128);
        __syncwarp();

        int t = t0;
        while (t + 16 <= t1) {
            float buf[16];
            #pragma unroll
            for (int j = 0; j < 16; j++)
                buf[j] = lif[(size_t)(t + j) * N_OUT + n];
            #pragma unroll
            for (int j = 0; j < 16; j++)
                out[(size_t)(t + j) * N_OUT + n] =
                    lif_step(buf[j], v, refrac, dt_tau, rest, th, rst, trf);
            t += 16;
        }
        while (t < t1) {
            float inp = lif[(size_t)t * N_OUT + n];
            out[(size_t)t * N_OUT + n] =
                lif_step(inp, v, refrac, dt_tau, rest, th, rst, trf);
            t++;
        }
    }

    // self-clean: last scan CTA to finish resets flags for the next replay.
    // Safe: every CTA has finished ALL flag reads before arriving here, and
    // the next replay's GEMM launches only after this kernel completes (join).
    __syncwarp();
    if (threadIdx.x == 0) {
        if (atomicAdd(&g_scan_done, 1) == SCAN_CTAS - 1) {
            #pragma unroll
            for (int b = 0; b < M_BLK; b++) g_flags[b] = 0;
            __threadfence();
            g_scan_done = 0;
            __threadfence();
        }
    }
}

// ---------------------------------------------------------------------------
extern "C" void kernel_launch(void* const* d_in, const int* in_sizes, int n_in,
                              void* d_out, int out_size)
{
    const float* x       = (const float*)d_in[0];
    const float* weight  = (const float*)d_in[1];
    const float* v_th    = (const float*)d_in[2];
    const float* v_rest  = (const float*)d_in[3];
    const float* v_reset = (const float*)d_in[4];
    const float* t_ref   = (const float*)d_in[5];
    const float* tau     = (const float*)d_in[6];
    float* out = (float*)d_out;

    float* lif_ptr = nullptr;
    cudaGetSymbolAddress((void**)&lif_ptr, g_lif);

    // fork resources (no device memory)
    cudaStream_t s2;
    cudaEvent_t ev0, ev1;
    cudaStreamCreateWithFlags(&s2, cudaStreamNonBlocking);
    cudaEventCreateWithFlags(&ev0, cudaEventDisableTiming);
    cudaEventCreateWithFlags(&ev1, cudaEventDisableTiming);

    // fork (flags already zero: static init on first call, scan-side reset after)
    cudaEventRecord(ev0, 0);
    cudaStreamWaitEvent(s2, ev0, 0);

    // branch A (main stream): GEMM producer — starts immediately
    dim3 grid(N_OUT / BN, (T_STEPS + BM - 1) / BM);
    gemm_nt_kernel<<<grid, 256>>>(x, weight, lif_ptr, T_STEPS, N_OUT, N_IN);

    // branch B (s2): scan consumer, polls per-m-block flags
    lif_scan_kernel<<<128, 32, 0, s2>>>(lif_ptr, out,
                                        v_th, v_rest, v_reset, t_ref, tau);

    // join
    cudaEventRecord(ev1, s2);
    cudaStreamWaitEvent(0, ev1, 0);
}